// round 10
// baseline (speedup 1.0000x reference)
#include <cuda_runtime.h>
#include <cuda_bf16.h>
#include <cstdint>
#include <math.h>

#define BB 2048
#define TT 128
#define SS 64
#define AA 32
#define G3 192
#define HH 128
#define OO 256

#define DEV __device__ __forceinline__

DEV uint32_t tf32b(float x) {
    uint32_t u;
    asm("cvt.rna.tf32.f32 %0, %1;" : "=r"(u) : "f"(x));
    return u;
}
DEV float tf32r(float x) { return __uint_as_float(tf32b(x)); }

// packed pair index: element u (0..7) of an 8-group -> slot in float2-pair array
DEV int pidx(int u) { return (u < 4) ? (u << 1) : (((u - 4) << 1) | 1); }

DEV float bfhi(float x) { return __bfloat162float(__float2bfloat16_rn(x)); }
DEV uint32_t bfpack(float x, float y) {
    __nv_bfloat162 t = __floats2bfloat162_rn(x, y);
    return *reinterpret_cast<uint32_t*>(&t);
}

DEV void cp_async4(uint32_t smem_addr, const void* gptr) {
    asm volatile("cp.async.ca.shared.global [%0], [%1], 4;"
                 :: "r"(smem_addr), "l"(gptr));
}

DEV void mma_tf32(float* d, const uint32_t* a, uint32_t b0, uint32_t b1) {
    asm volatile(
        "mma.sync.aligned.m16n8k8.row.col.f32.tf32.tf32.f32 "
        "{%0,%1,%2,%3}, {%4,%5,%6,%7}, {%8,%9}, {%0,%1,%2,%3};"
        : "+f"(d[0]), "+f"(d[1]), "+f"(d[2]), "+f"(d[3])
        : "r"(a[0]), "r"(a[1]), "r"(a[2]), "r"(a[3]), "r"(b0), "r"(b1));
}

DEV void mma_bf16(float* d, const uint32_t* a, uint32_t b0, uint32_t b1) {
    asm volatile(
        "mma.sync.aligned.m16n8k16.row.col.f32.bf16.bf16.f32 "
        "{%0,%1,%2,%3}, {%4,%5,%6,%7}, {%8,%9}, {%0,%1,%2,%3};"
        : "+f"(d[0]), "+f"(d[1]), "+f"(d[2]), "+f"(d[3])
        : "r"(a[0]), "r"(a[1]), "r"(a[2]), "r"(a[3]), "r"(b0), "r"(b1));
}

// ---------------------------------------------------------------------------
// Kernel 1: GRU scan, bf16x3 mma.m16n8k16. 128 CTAs x 16 rows, 256 threads.
// (unchanged — measured ~192 us)
// ---------------------------------------------------------------------------
struct ScanSmem {
    uint32_t hhp[2][4][16][8];
    uint32_t hlp[2][4][16][8];
    uint32_t ahp[2][2][16][8];
    uint32_t alp[2][2][16][8];
    uint32_t loIp[6][192][8];
    uint32_t loHp[4][192][8];
};

__global__ void __launch_bounds__(256, 1)
scan_kernel(const float* __restrict__ initial_state,
            const float* __restrict__ actions,
            const float* __restrict__ W_ih,
            const float* __restrict__ W_hh,
            const float* __restrict__ b_ih,
            const float* __restrict__ b_hh,
            float* __restrict__ states) {
    extern __shared__ char smem_raw[];
    ScanSmem& sm = *reinterpret_cast<ScanSmem*>(smem_raw);
    const int tid = threadIdx.x;
    const int w = tid >> 5;
    const int lane = tid & 31;
    const int gid = lane >> 2;
    const int t4 = lane & 3;
    const int b0 = blockIdx.x * 16;

    for (int i = tid; i < 192 * 48; i += 256) {
        const int n = i / 48, p = i % 48;
        const float v0 = W_ih[n * 96 + 2 * p];
        const float v1 = W_ih[n * 96 + 2 * p + 1];
        sm.loIp[p >> 3][n][pidx(p & 7)] = bfpack(v0 - bfhi(v0), v1 - bfhi(v1));
    }
    for (int i = tid; i < 192 * 32; i += 256) {
        const int n = i / 32, p = i % 32;
        const float v0 = W_hh[n * 64 + 2 * p];
        const float v1 = W_hh[n * 64 + 2 * p + 1];
        sm.loHp[p >> 3][n][pidx(p & 7)] = bfpack(v0 - bfhi(v0), v1 - bfhi(v1));
    }

    uint32_t BI[3][6][2], BH[3][4][2];
    #pragma unroll
    for (int ti = 0; ti < 3; ++ti) {
        const int n = w * 8 + ti * 64 + gid;
        #pragma unroll
        for (int kc = 0; kc < 6; ++kc) {
            const int k0 = kc * 16 + 2 * t4;
            BI[ti][kc][0] = bfpack(bfhi(W_ih[n * 96 + k0]),     bfhi(W_ih[n * 96 + k0 + 1]));
            BI[ti][kc][1] = bfpack(bfhi(W_ih[n * 96 + k0 + 8]), bfhi(W_ih[n * 96 + k0 + 9]));
        }
        #pragma unroll
        for (int kc = 0; kc < 4; ++kc) {
            const int k0 = kc * 16 + 2 * t4;
            BH[ti][kc][0] = bfpack(bfhi(W_hh[n * 64 + k0]),     bfhi(W_hh[n * 64 + k0 + 1]));
            BH[ti][kc][1] = bfpack(bfhi(W_hh[n * 64 + k0 + 8]), bfhi(W_hh[n * 64 + k0 + 9]));
        }
    }

    const int c = w * 8 + t4 * 2;
    const float br_[2]  = {b_ih[c] + b_hh[c],           b_ih[c + 1] + b_hh[c + 1]};
    const float bz_[2]  = {b_ih[64 + c] + b_hh[64 + c], b_ih[65 + c] + b_hh[65 + c]};
    const float biN_[2] = {b_ih[128 + c], b_ih[129 + c]};
    const float bhN_[2] = {b_hh[128 + c], b_hh[129 + c]};

    for (int i = tid; i < 16 * 32; i += 256) {
        const int r = i >> 5, p = i & 31;
        const float v0 = initial_state[(long)(b0 + r) * SS + 2 * p];
        const float v1 = initial_state[(long)(b0 + r) * SS + 2 * p + 1];
        states[(long)(b0 + r) * ((TT + 1) * SS) + 2 * p]     = v0;
        states[(long)(b0 + r) * ((TT + 1) * SS) + 2 * p + 1] = v1;
        const float h0 = bfhi(v0), h1 = bfhi(v1);
        sm.hhp[0][p >> 3][r][pidx(p & 7)] = bfpack(h0, h1);
        sm.hlp[0][p >> 3][r][pidx(p & 7)] = bfpack(v0 - h0, v1 - h1);
    }
    float hreg[4];
    hreg[0] = initial_state[(long)(b0 + gid) * SS + c];
    hreg[1] = initial_state[(long)(b0 + gid) * SS + c + 1];
    hreg[2] = initial_state[(long)(b0 + gid + 8) * SS + c];
    hreg[3] = initial_state[(long)(b0 + gid + 8) * SS + c + 1];

    const int pr = tid >> 4;
    const int pp = tid & 15;
    const int akc = pp >> 3, aslot = pidx(pp & 7);
    {
        const float2 v = *reinterpret_cast<const float2*>(
            &actions[((long)(b0 + pr) * TT) * AA + 2 * pp]);
        const float h0 = bfhi(v.x), h1 = bfhi(v.y);
        sm.ahp[0][akc][pr][aslot] = bfpack(h0, h1);
        sm.alp[0][akc][pr][aslot] = bfpack(v.x - h0, v.y - h1);
    }
    __syncthreads();

    const int hkc   = (w * 4 + t4) >> 3;
    const int hslot = pidx((w * 4 + t4) & 7);

    for (int t = 0; t < TT; ++t) {
        const int cur = t & 1, nxt = cur ^ 1;
        const bool dopref = (t + 1 < TT);
        float2 pref = make_float2(0.f, 0.f);
        if (dopref)
            pref = *reinterpret_cast<const float2*>(
                &actions[((long)(b0 + pr) * TT + (t + 1)) * AA + 2 * pp]);

        float aR[4]  = {0.f, 0.f, 0.f, 0.f};
        float aZ[4]  = {0.f, 0.f, 0.f, 0.f};
        float aNI[4] = {0.f, 0.f, 0.f, 0.f};
        float aNH[4] = {0.f, 0.f, 0.f, 0.f};

        #pragma unroll
        for (int kc = 0; kc < 6; ++kc) {
            uint2 h0, h1, l0, l1;
            if (kc < 4) {
                h0 = *reinterpret_cast<const uint2*>(&sm.hhp[cur][kc][gid][2 * t4]);
                h1 = *reinterpret_cast<const uint2*>(&sm.hhp[cur][kc][gid + 8][2 * t4]);
                l0 = *reinterpret_cast<const uint2*>(&sm.hlp[cur][kc][gid][2 * t4]);
                l1 = *reinterpret_cast<const uint2*>(&sm.hlp[cur][kc][gid + 8][2 * t4]);
            } else {
                h0 = *reinterpret_cast<const uint2*>(&sm.ahp[cur][kc - 4][gid][2 * t4]);
                h1 = *reinterpret_cast<const uint2*>(&sm.ahp[cur][kc - 4][gid + 8][2 * t4]);
                l0 = *reinterpret_cast<const uint2*>(&sm.alp[cur][kc - 4][gid][2 * t4]);
                l1 = *reinterpret_cast<const uint2*>(&sm.alp[cur][kc - 4][gid + 8][2 * t4]);
            }
            const uint32_t ah[4] = {h0.x, h1.x, h0.y, h1.y};
            const uint32_t al[4] = {l0.x, l1.x, l0.y, l1.y};

            #pragma unroll
            for (int ti = 0; ti < 3; ++ti) {
                float* acc = (ti == 0) ? aR : (ti == 1) ? aZ : aNI;
                const int n = w * 8 + ti * 64 + gid;
                const uint2 bl = *reinterpret_cast<const uint2*>(&sm.loIp[kc][n][2 * t4]);
                mma_bf16(acc, ah, BI[ti][kc][0], BI[ti][kc][1]);
                mma_bf16(acc, al, BI[ti][kc][0], BI[ti][kc][1]);
                mma_bf16(acc, ah, bl.x, bl.y);
            }
            if (kc < 4) {
                #pragma unroll
                for (int ti = 0; ti < 3; ++ti) {
                    float* acc = (ti == 0) ? aR : (ti == 1) ? aZ : aNH;
                    const int n = w * 8 + ti * 64 + gid;
                    const uint2 bl = *reinterpret_cast<const uint2*>(&sm.loHp[kc][n][2 * t4]);
                    mma_bf16(acc, ah, BH[ti][kc][0], BH[ti][kc][1]);
                    mma_bf16(acc, al, BH[ti][kc][0], BH[ti][kc][1]);
                    mma_bf16(acc, ah, bl.x, bl.y);
                }
            }
        }

        #pragma unroll
        for (int v = 0; v < 4; ++v) {
            const int p = v & 1;
            const float sr = aR[v] + br_[p];
            const float sz = aZ[v] + bz_[p];
            const float rg = __fdividef(1.f, 1.f + __expf(-sr));
            const float zg = __fdividef(1.f, 1.f + __expf(-sz));
            const float narg = aNI[v] + biN_[p] + rg * (aNH[v] + bhN_[p]);
            const float e2 = __expf(2.f * narg);
            const float ng = 1.f - __fdividef(2.f, e2 + 1.f);
            hreg[v] = (1.f - zg) * ng + zg * hreg[v];
        }

        {
            const float hi0 = bfhi(hreg[0]), hi1 = bfhi(hreg[1]);
            const float hi2 = bfhi(hreg[2]), hi3 = bfhi(hreg[3]);
            sm.hhp[nxt][hkc][gid][hslot]     = bfpack(hi0, hi1);
            sm.hhp[nxt][hkc][gid + 8][hslot] = bfpack(hi2, hi3);
            sm.hlp[nxt][hkc][gid][hslot]     = bfpack(hreg[0] - hi0, hreg[1] - hi1);
            sm.hlp[nxt][hkc][gid + 8][hslot] = bfpack(hreg[2] - hi2, hreg[3] - hi3);
        }
        *reinterpret_cast<float2*>(
            &states[((long)(b0 + gid) * (TT + 1) + t + 1) * SS + c]) =
            make_float2(hreg[0], hreg[1]);
        *reinterpret_cast<float2*>(
            &states[((long)(b0 + gid + 8) * (TT + 1) + t + 1) * SS + c]) =
            make_float2(hreg[2], hreg[3]);
        if (dopref) {
            const float h0 = bfhi(pref.x), h1 = bfhi(pref.y);
            sm.ahp[nxt][akc][pr][aslot] = bfpack(h0, h1);
            sm.alp[nxt][akc][pr][aslot] = bfpack(pref.x - h0, pref.y - h1);
        }
        __syncthreads();
    }
}

// ---------------------------------------------------------------------------
// Kernel 2: heads, 1024 threads (32 warps), 128-row tile, smem reuse +
// cp.async double-buffered W2 quarter pipeline. Smem = 134656 B, 1 CTA/SM.
// ---------------------------------------------------------------------------
struct HeadSmem {
    float W1A1[16384];      // L1 weights [8][256][8] -> A1p [16][128][8]
    float XpWQ[16384];      // Xp [8][128][8] -> W2 quarter double-buffer [2][16][64][8]
    float b1s[256];
    float w2r[64];
    float w2s[64];
    float psum[2][2][128];  // [head][half][row]
};

__global__ void __launch_bounds__(1024, 1)
heads_kernel(const float* __restrict__ states,
             const float* __restrict__ dec_w1, const float* __restrict__ dec_b1,
             const float* __restrict__ dec_w2, const float* __restrict__ dec_b2,
             const float* __restrict__ rew_w1, const float* __restrict__ rew_b1,
             const float* __restrict__ rew_w2, const float* __restrict__ rew_b2,
             const float* __restrict__ saf_w1, const float* __restrict__ saf_b1,
             const float* __restrict__ saf_w2, const float* __restrict__ saf_b2,
             float* __restrict__ obs, float* __restrict__ rew,
             float* __restrict__ saf) {
    extern __shared__ char smem_raw[];
    HeadSmem& sm = *reinterpret_cast<HeadSmem*>(smem_raw);
    const int tid = threadIdx.x;
    const int m0 = blockIdx.x * 128;

    // ---- prologue staging ----
    for (int i = tid; i < 128 * 16; i += 1024) {
        const int r = i >> 4, c4 = (i & 15) * 4;
        const int m = m0 + r, b = m >> 7, t = m & 127;
        const float4 v = *reinterpret_cast<const float4*>(
            &states[((long)b * (TT + 1) + t + 1) * SS + c4]);
        float* p = &sm.XpWQ[(c4 >> 3) * 1024 + r * 8];
        if ((c4 & 4) == 0) {
            p[0] = tf32r(v.x); p[2] = tf32r(v.y); p[4] = tf32r(v.z); p[6] = tf32r(v.w);
        } else {
            p[1] = tf32r(v.x); p[3] = tf32r(v.y); p[5] = tf32r(v.z); p[7] = tf32r(v.w);
        }
    }
    for (int i = tid; i < 256 * 64; i += 1024) {
        const int n = i >> 6, k = i & 63;
        float wv;
        if (n < 128)      wv = dec_w1[n * 64 + k];
        else if (n < 192) wv = rew_w1[(n - 128) * 64 + k];
        else              wv = saf_w1[(n - 192) * 64 + k];
        sm.W1A1[(k >> 3) * 2048 + n * 8 + pidx(k & 7)] = tf32r(wv);
    }
    for (int i = tid; i < 256; i += 1024)
        sm.b1s[i] = (i < 128) ? dec_b1[i] : ((i < 192) ? rew_b1[i - 128] : saf_b1[i - 192]);
    for (int i = tid; i < 64; i += 1024) { sm.w2r[i] = rew_w2[i]; sm.w2s[i] = saf_w2[i]; }
    __syncthreads();

    const int lane = tid & 31;
    const int w = tid >> 5;        // 32 warps
    const int wr = w & 3;          // 4 row groups of 32
    const int wc = w >> 2;         // 8 col groups
    const int gid = lane >> 2;
    const int t4 = lane & 3;
    const int i0p = pidx(t4 * 2);
    const int i1p = pidx(t4 * 2 + 1);

    // ---- Layer 1: (128x64) @ (64x256), 32 cols per warp ----
    float acc[2][4][4];
    #pragma unroll
    for (int mt = 0; mt < 2; ++mt)
        #pragma unroll
        for (int nt = 0; nt < 4; ++nt)
            #pragma unroll
            for (int q = 0; q < 4; ++q) acc[mt][nt][q] = 0.f;

    #pragma unroll
    for (int ks = 0; ks < 8; ++ks) {
        uint32_t a[2][4];
        #pragma unroll
        for (int mt = 0; mt < 2; ++mt) {
            const int R = wr * 32 + mt * 16;
            const float2 f0 = *reinterpret_cast<const float2*>(
                &sm.XpWQ[ks * 1024 + (R + gid) * 8 + 2 * t4]);
            const float2 f1 = *reinterpret_cast<const float2*>(
                &sm.XpWQ[ks * 1024 + (R + gid + 8) * 8 + 2 * t4]);
            a[mt][0] = __float_as_uint(f0.x); a[mt][1] = __float_as_uint(f1.x);
            a[mt][2] = __float_as_uint(f0.y); a[mt][3] = __float_as_uint(f1.y);
        }
        #pragma unroll
        for (int nt = 0; nt < 4; ++nt) {
            const int n0 = wc * 32 + nt * 8;
            const float2 bv = *reinterpret_cast<const float2*>(
                &sm.W1A1[ks * 2048 + (n0 + gid) * 8 + 2 * t4]);
            mma_tf32(acc[0][nt], a[0], __float_as_uint(bv.x), __float_as_uint(bv.y));
            mma_tf32(acc[1][nt], a[1], __float_as_uint(bv.x), __float_as_uint(bv.y));
        }
    }
    __syncthreads();   // W1 + Xp regions now dead (acc in registers)

    const uint32_t wq0 = (uint32_t)__cvta_generic_to_shared(&sm.XpWQ[0]);
    // async-stage W2 quarter 0 into buf0
    for (int i = tid; i < 64 * 128; i += 1024) {
        const int n = i >> 7, k = i & 127;
        cp_async4(wq0 + 4u * ((k >> 3) * 512 + n * 8 + pidx(k & 7)),
                  &dec_w2[n * 128 + k]);
    }
    asm volatile("cp.async.commit_group;");

    // ---- L1 epilogue ----
    if (wc < 4) {
        // dec cols -> A1p in W1A1 region
        #pragma unroll
        for (int mt = 0; mt < 2; ++mt) {
            const int R = wr * 32 + mt * 16;
            #pragma unroll
            for (int nt = 0; nt < 4; ++nt) {
                const int ks2 = wc * 4 + nt;
                const int col = wc * 32 + nt * 8 + t4 * 2;
                const float bA = sm.b1s[col], bBv = sm.b1s[col + 1];
                sm.W1A1[ks2 * 1024 + (R + gid) * 8 + i0p]     = tf32r(fmaxf(acc[mt][nt][0] + bA, 0.f));
                sm.W1A1[ks2 * 1024 + (R + gid) * 8 + i1p]     = tf32r(fmaxf(acc[mt][nt][1] + bBv, 0.f));
                sm.W1A1[ks2 * 1024 + (R + gid + 8) * 8 + i0p] = tf32r(fmaxf(acc[mt][nt][2] + bA, 0.f));
                sm.W1A1[ks2 * 1024 + (R + gid + 8) * 8 + i1p] = tf32r(fmaxf(acc[mt][nt][3] + bBv, 0.f));
            }
        }
    } else {
        // rew (wc 4,5) / saf (wc 6,7): partial dot over this warp's 32 cols
        const int head = (wc >= 6) ? 1 : 0;
        const int wl = wc & 1;
        const float* w2v = head ? sm.w2s : sm.w2r;
        const int bbase = 128 + head * 64;
        #pragma unroll
        for (int mt = 0; mt < 2; ++mt) {
            float plo = 0.f, phi = 0.f;
            #pragma unroll
            for (int nt = 0; nt < 4; ++nt) {
                const int l = wl * 32 + nt * 8 + t4 * 2;
                const float bA = sm.b1s[bbase + l], bBv = sm.b1s[bbase + l + 1];
                const float v00 = fmaxf(acc[mt][nt][0] + bA, 0.f);
                const float v01 = fmaxf(acc[mt][nt][1] + bBv, 0.f);
                const float v10 = fmaxf(acc[mt][nt][2] + bA, 0.f);
                const float v11 = fmaxf(acc[mt][nt][3] + bBv, 0.f);
                plo = fmaf(v00, w2v[l], fmaf(v01, w2v[l + 1], plo));
                phi = fmaf(v10, w2v[l], fmaf(v11, w2v[l + 1], phi));
            }
            plo += __shfl_xor_sync(0xFFFFFFFFu, plo, 1);
            plo += __shfl_xor_sync(0xFFFFFFFFu, plo, 2);
            phi += __shfl_xor_sync(0xFFFFFFFFu, phi, 1);
            phi += __shfl_xor_sync(0xFFFFFFFFu, phi, 2);
            if (t4 == 0) {
                const int R = wr * 32 + mt * 16;
                sm.psum[head][wl][R + gid]     = plo;
                sm.psum[head][wl][R + gid + 8] = phi;
            }
        }
    }

    // async-stage W2 quarter 1 into buf1
    for (int i = tid; i < 64 * 128; i += 1024) {
        const int n = i >> 7, k = i & 127;
        cp_async4(wq0 + 4u * (8192 + (k >> 3) * 512 + n * 8 + pidx(k & 7)),
                  &dec_w2[(64 + n) * 128 + k]);
    }
    asm volatile("cp.async.commit_group;");
    asm volatile("cp.async.wait_group 1;" ::: "memory");
    __syncthreads();   // A1p + psum visible; quarter 0 loaded

    // finalize rew/saf
    if (tid < 256) {
        const int head = tid >> 7, r = tid & 127;
        const float b2 = head ? __ldg(&saf_b2[0]) : __ldg(&rew_b2[0]);
        const float v = sm.psum[head][0][r] + sm.psum[head][1][r] + b2;
        (head ? saf : rew)[m0 + r] = v;
    }

    // ---- Layer 2: 4 quarters of 64 cols, double-buffered ----
    #define L2_QUARTER(bufofs, q)                                              \
    {                                                                          \
        float acc2[2][4];                                                      \
        acc2[0][0] = acc2[0][1] = acc2[0][2] = acc2[0][3] = 0.f;               \
        acc2[1][0] = acc2[1][1] = acc2[1][2] = acc2[1][3] = 0.f;               \
        _Pragma("unroll")                                                      \
        for (int ks = 0; ks < 16; ++ks) {                                      \
            uint32_t a[2][4];                                                  \
            _Pragma("unroll")                                                  \
            for (int mt = 0; mt < 2; ++mt) {                                   \
                const int R = wr * 32 + mt * 16;                               \
                const float2 f0 = *reinterpret_cast<const float2*>(            \
                    &sm.W1A1[ks * 1024 + (R + gid) * 8 + 2 * t4]);             \
                const float2 f1 = *reinterpret_cast<const float2*>(            \
                    &sm.W1A1[ks * 1024 + (R + gid + 8) * 8 + 2 * t4]);         \
                a[mt][0] = __float_as_uint(f0.x); a[mt][1] = __float_as_uint(f1.x); \
                a[mt][2] = __float_as_uint(f0.y); a[mt][3] = __float_as_uint(f1.y); \
            }                                                                  \
            const float2 bv = *reinterpret_cast<const float2*>(                \
                &sm.XpWQ[(bufofs) + ks * 512 + (wc * 8 + gid) * 8 + 2 * t4]);  \
            mma_tf32(acc2[0], a[0], __float_as_uint(bv.x), __float_as_uint(bv.y)); \
            mma_tf32(acc2[1], a[1], __float_as_uint(bv.x), __float_as_uint(bv.y)); \
        }                                                                      \
        _Pragma("unroll")                                                      \
        for (int mt = 0; mt < 2; ++mt) {                                       \
            const int R = wr * 32 + mt * 16;                                   \
            const int cg = (q) * 64 + wc * 8 + t4 * 2;                         \
            const float2 b2v = *reinterpret_cast<const float2*>(&dec_b2[cg]);  \
            *reinterpret_cast<float2*>(&obs[(long)(m0 + R + gid) * OO + cg]) = \
                make_float2(acc2[mt][0] + b2v.x, acc2[mt][1] + b2v.y);         \
            *reinterpret_cast<float2*>(&obs[(long)(m0 + R + gid + 8) * OO + cg]) = \
                make_float2(acc2[mt][2] + b2v.x, acc2[mt][3] + b2v.y);         \
        }                                                                      \
    }

    L2_QUARTER(0, 0)
    asm volatile("cp.async.wait_group 0;" ::: "memory");
    __syncthreads();   // buf0 reads done; quarter 1 visible

    // stage quarter 2 -> buf0
    for (int i = tid; i < 64 * 128; i += 1024) {
        const int n = i >> 7, k = i & 127;
        cp_async4(wq0 + 4u * ((k >> 3) * 512 + n * 8 + pidx(k & 7)),
                  &dec_w2[(128 + n) * 128 + k]);
    }
    asm volatile("cp.async.commit_group;");

    L2_QUARTER(8192, 1)
    __syncthreads();   // buf1 reads done

    // stage quarter 3 -> buf1
    for (int i = tid; i < 64 * 128; i += 1024) {
        const int n = i >> 7, k = i & 127;
        cp_async4(wq0 + 4u * (8192 + (k >> 3) * 512 + n * 8 + pidx(k & 7)),
                  &dec_w2[(192 + n) * 128 + k]);
    }
    asm volatile("cp.async.commit_group;");
    asm volatile("cp.async.wait_group 1;" ::: "memory");
    __syncthreads();   // quarter 2 visible

    L2_QUARTER(0, 2)
    asm volatile("cp.async.wait_group 0;" ::: "memory");
    __syncthreads();   // quarter 3 visible

    L2_QUARTER(8192, 3)
    #undef L2_QUARTER
}

// ---------------------------------------------------------------------------
extern "C" void kernel_launch(void* const* d_in, const int* in_sizes, int n_in,
                              void* d_out, int out_size) {
    const float* initial_state = (const float*)d_in[0];
    const float* actions = (const float*)d_in[1];
    const float* W_ih = (const float*)d_in[2];
    const float* W_hh = (const float*)d_in[3];
    const float* b_ih = (const float*)d_in[4];
    const float* b_hh = (const float*)d_in[5];
    const float* dec_w1 = (const float*)d_in[6];
    const float* dec_b1 = (const float*)d_in[7];
    const float* dec_w2 = (const float*)d_in[8];
    const float* dec_b2 = (const float*)d_in[9];
    const float* rew_w1 = (const float*)d_in[10];
    const float* rew_b1 = (const float*)d_in[11];
    const float* rew_w2 = (const float*)d_in[12];
    const float* rew_b2 = (const float*)d_in[13];
    const float* saf_w1 = (const float*)d_in[14];
    const float* saf_b1 = (const float*)d_in[15];
    const float* saf_w2 = (const float*)d_in[16];
    const float* saf_b2 = (const float*)d_in[17];

    float* out = (float*)d_out;
    float* states = out;
    float* obs = out + (long)BB * (TT + 1) * SS;
    float* rew = obs + (long)BB * TT * OO;
    float* saf = rew + (long)BB * TT;

    cudaFuncSetAttribute(scan_kernel, cudaFuncAttributeMaxDynamicSharedMemorySize,
                         (int)sizeof(ScanSmem));
    cudaFuncSetAttribute(heads_kernel, cudaFuncAttributeMaxDynamicSharedMemorySize,
                         (int)sizeof(HeadSmem));

    scan_kernel<<<BB / 16, 256, sizeof(ScanSmem)>>>(
        initial_state, actions, W_ih, W_hh, b_ih, b_hh, states);
    heads_kernel<<<(BB * TT) / 128, 1024, sizeof(HeadSmem)>>>(
        states, dec_w1, dec_b1, dec_w2, dec_b2,
        rew_w1, rew_b1, rew_w2, rew_b2,
        saf_w1, saf_b1, saf_w2, saf_b2,
        obs, rew, saf);
}

// round 15
// speedup vs baseline: 1.2479x; 1.2479x over previous
#include <cuda_runtime.h>
#include <cuda_bf16.h>
#include <cstdint>
#include <math.h>

#define BB 2048
#define TT 128
#define SS 64
#define AA 32
#define G3 192
#define HH 128
#define OO 256

#define DEV __device__ __forceinline__

DEV uint32_t tf32b(float x) {
    uint32_t u;
    asm("cvt.rna.tf32.f32 %0, %1;" : "=r"(u) : "f"(x));
    return u;
}
DEV float tf32r(float x) { return __uint_as_float(tf32b(x)); }

// packed pair index: element u (0..7) of an 8-group -> slot in float2-pair array
DEV int pidx(int u) { return (u < 4) ? (u << 1) : (((u - 4) << 1) | 1); }

DEV float bfhi(float x) { return __bfloat162float(__float2bfloat16_rn(x)); }
DEV uint32_t bfpack(float x, float y) {
    __nv_bfloat162 t = __floats2bfloat162_rn(x, y);
    return *reinterpret_cast<uint32_t*>(&t);
}

DEV void cp_async16(uint32_t smem_addr, const void* gptr) {
    asm volatile("cp.async.cg.shared.global [%0], [%1], 16;"
                 :: "r"(smem_addr), "l"(gptr));
}

DEV void mma_tf32(float* d, const uint32_t* a, uint32_t b0, uint32_t b1) {
    asm volatile(
        "mma.sync.aligned.m16n8k8.row.col.f32.tf32.tf32.f32 "
        "{%0,%1,%2,%3}, {%4,%5,%6,%7}, {%8,%9}, {%0,%1,%2,%3};"
        : "+f"(d[0]), "+f"(d[1]), "+f"(d[2]), "+f"(d[3])
        : "r"(a[0]), "r"(a[1]), "r"(a[2]), "r"(a[3]), "r"(b0), "r"(b1));
}

DEV void mma_bf16(float* d, const uint32_t* a, uint32_t b0, uint32_t b1) {
    asm volatile(
        "mma.sync.aligned.m16n8k16.row.col.f32.bf16.bf16.f32 "
        "{%0,%1,%2,%3}, {%4,%5,%6,%7}, {%8,%9}, {%0,%1,%2,%3};"
        : "+f"(d[0]), "+f"(d[1]), "+f"(d[2]), "+f"(d[3])
        : "r"(a[0]), "r"(a[1]), "r"(a[2]), "r"(a[3]), "r"(b0), "r"(b1));
}

// ---------------------------------------------------------------------------
// Kernel 1: GRU scan, bf16x3 mma.m16n8k16. 128 CTAs x 16 rows, 256 threads.
// (unchanged — measured ~192 us)
// ---------------------------------------------------------------------------
struct ScanSmem {
    uint32_t hhp[2][4][16][8];
    uint32_t hlp[2][4][16][8];
    uint32_t ahp[2][2][16][8];
    uint32_t alp[2][2][16][8];
    uint32_t loIp[6][192][8];
    uint32_t loHp[4][192][8];
};

__global__ void __launch_bounds__(256, 1)
scan_kernel(const float* __restrict__ initial_state,
            const float* __restrict__ actions,
            const float* __restrict__ W_ih,
            const float* __restrict__ W_hh,
            const float* __restrict__ b_ih,
            const float* __restrict__ b_hh,
            float* __restrict__ states) {
    extern __shared__ char smem_raw[];
    ScanSmem& sm = *reinterpret_cast<ScanSmem*>(smem_raw);
    const int tid = threadIdx.x;
    const int w = tid >> 5;
    const int lane = tid & 31;
    const int gid = lane >> 2;
    const int t4 = lane & 3;
    const int b0 = blockIdx.x * 16;

    for (int i = tid; i < 192 * 48; i += 256) {
        const int n = i / 48, p = i % 48;
        const float v0 = W_ih[n * 96 + 2 * p];
        const float v1 = W_ih[n * 96 + 2 * p + 1];
        sm.loIp[p >> 3][n][pidx(p & 7)] = bfpack(v0 - bfhi(v0), v1 - bfhi(v1));
    }
    for (int i = tid; i < 192 * 32; i += 256) {
        const int n = i / 32, p = i % 32;
        const float v0 = W_hh[n * 64 + 2 * p];
        const float v1 = W_hh[n * 64 + 2 * p + 1];
        sm.loHp[p >> 3][n][pidx(p & 7)] = bfpack(v0 - bfhi(v0), v1 - bfhi(v1));
    }

    uint32_t BI[3][6][2], BH[3][4][2];
    #pragma unroll
    for (int ti = 0; ti < 3; ++ti) {
        const int n = w * 8 + ti * 64 + gid;
        #pragma unroll
        for (int kc = 0; kc < 6; ++kc) {
            const int k0 = kc * 16 + 2 * t4;
            BI[ti][kc][0] = bfpack(bfhi(W_ih[n * 96 + k0]),     bfhi(W_ih[n * 96 + k0 + 1]));
            BI[ti][kc][1] = bfpack(bfhi(W_ih[n * 96 + k0 + 8]), bfhi(W_ih[n * 96 + k0 + 9]));
        }
        #pragma unroll
        for (int kc = 0; kc < 4; ++kc) {
            const int k0 = kc * 16 + 2 * t4;
            BH[ti][kc][0] = bfpack(bfhi(W_hh[n * 64 + k0]),     bfhi(W_hh[n * 64 + k0 + 1]));
            BH[ti][kc][1] = bfpack(bfhi(W_hh[n * 64 + k0 + 8]), bfhi(W_hh[n * 64 + k0 + 9]));
        }
    }

    const int c = w * 8 + t4 * 2;
    const float br_[2]  = {b_ih[c] + b_hh[c],           b_ih[c + 1] + b_hh[c + 1]};
    const float bz_[2]  = {b_ih[64 + c] + b_hh[64 + c], b_ih[65 + c] + b_hh[65 + c]};
    const float biN_[2] = {b_ih[128 + c], b_ih[129 + c]};
    const float bhN_[2] = {b_hh[128 + c], b_hh[129 + c]};

    for (int i = tid; i < 16 * 32; i += 256) {
        const int r = i >> 5, p = i & 31;
        const float v0 = initial_state[(long)(b0 + r) * SS + 2 * p];
        const float v1 = initial_state[(long)(b0 + r) * SS + 2 * p + 1];
        states[(long)(b0 + r) * ((TT + 1) * SS) + 2 * p]     = v0;
        states[(long)(b0 + r) * ((TT + 1) * SS) + 2 * p + 1] = v1;
        const float h0 = bfhi(v0), h1 = bfhi(v1);
        sm.hhp[0][p >> 3][r][pidx(p & 7)] = bfpack(h0, h1);
        sm.hlp[0][p >> 3][r][pidx(p & 7)] = bfpack(v0 - h0, v1 - h1);
    }
    float hreg[4];
    hreg[0] = initial_state[(long)(b0 + gid) * SS + c];
    hreg[1] = initial_state[(long)(b0 + gid) * SS + c + 1];
    hreg[2] = initial_state[(long)(b0 + gid + 8) * SS + c];
    hreg[3] = initial_state[(long)(b0 + gid + 8) * SS + c + 1];

    const int pr = tid >> 4;
    const int pp = tid & 15;
    const int akc = pp >> 3, aslot = pidx(pp & 7);
    {
        const float2 v = *reinterpret_cast<const float2*>(
            &actions[((long)(b0 + pr) * TT) * AA + 2 * pp]);
        const float h0 = bfhi(v.x), h1 = bfhi(v.y);
        sm.ahp[0][akc][pr][aslot] = bfpack(h0, h1);
        sm.alp[0][akc][pr][aslot] = bfpack(v.x - h0, v.y - h1);
    }
    __syncthreads();

    const int hkc   = (w * 4 + t4) >> 3;
    const int hslot = pidx((w * 4 + t4) & 7);

    for (int t = 0; t < TT; ++t) {
        const int cur = t & 1, nxt = cur ^ 1;
        const bool dopref = (t + 1 < TT);
        float2 pref = make_float2(0.f, 0.f);
        if (dopref)
            pref = *reinterpret_cast<const float2*>(
                &actions[((long)(b0 + pr) * TT + (t + 1)) * AA + 2 * pp]);

        float aR[4]  = {0.f, 0.f, 0.f, 0.f};
        float aZ[4]  = {0.f, 0.f, 0.f, 0.f};
        float aNI[4] = {0.f, 0.f, 0.f, 0.f};
        float aNH[4] = {0.f, 0.f, 0.f, 0.f};

        #pragma unroll
        for (int kc = 0; kc < 6; ++kc) {
            uint2 h0, h1, l0, l1;
            if (kc < 4) {
                h0 = *reinterpret_cast<const uint2*>(&sm.hhp[cur][kc][gid][2 * t4]);
                h1 = *reinterpret_cast<const uint2*>(&sm.hhp[cur][kc][gid + 8][2 * t4]);
                l0 = *reinterpret_cast<const uint2*>(&sm.hlp[cur][kc][gid][2 * t4]);
                l1 = *reinterpret_cast<const uint2*>(&sm.hlp[cur][kc][gid + 8][2 * t4]);
            } else {
                h0 = *reinterpret_cast<const uint2*>(&sm.ahp[cur][kc - 4][gid][2 * t4]);
                h1 = *reinterpret_cast<const uint2*>(&sm.ahp[cur][kc - 4][gid + 8][2 * t4]);
                l0 = *reinterpret_cast<const uint2*>(&sm.alp[cur][kc - 4][gid][2 * t4]);
                l1 = *reinterpret_cast<const uint2*>(&sm.alp[cur][kc - 4][gid + 8][2 * t4]);
            }
            const uint32_t ah[4] = {h0.x, h1.x, h0.y, h1.y};
            const uint32_t al[4] = {l0.x, l1.x, l0.y, l1.y};

            #pragma unroll
            for (int ti = 0; ti < 3; ++ti) {
                float* acc = (ti == 0) ? aR : (ti == 1) ? aZ : aNI;
                const int n = w * 8 + ti * 64 + gid;
                const uint2 bl = *reinterpret_cast<const uint2*>(&sm.loIp[kc][n][2 * t4]);
                mma_bf16(acc, ah, BI[ti][kc][0], BI[ti][kc][1]);
                mma_bf16(acc, al, BI[ti][kc][0], BI[ti][kc][1]);
                mma_bf16(acc, ah, bl.x, bl.y);
            }
            if (kc < 4) {
                #pragma unroll
                for (int ti = 0; ti < 3; ++ti) {
                    float* acc = (ti == 0) ? aR : (ti == 1) ? aZ : aNH;
                    const int n = w * 8 + ti * 64 + gid;
                    const uint2 bl = *reinterpret_cast<const uint2*>(&sm.loHp[kc][n][2 * t4]);
                    mma_bf16(acc, ah, BH[ti][kc][0], BH[ti][kc][1]);
                    mma_bf16(acc, al, BH[ti][kc][0], BH[ti][kc][1]);
                    mma_bf16(acc, ah, bl.x, bl.y);
                }
            }
        }

        #pragma unroll
        for (int v = 0; v < 4; ++v) {
            const int p = v & 1;
            const float sr = aR[v] + br_[p];
            const float sz = aZ[v] + bz_[p];
            const float rg = __fdividef(1.f, 1.f + __expf(-sr));
            const float zg = __fdividef(1.f, 1.f + __expf(-sz));
            const float narg = aNI[v] + biN_[p] + rg * (aNH[v] + bhN_[p]);
            const float e2 = __expf(2.f * narg);
            const float ng = 1.f - __fdividef(2.f, e2 + 1.f);
            hreg[v] = (1.f - zg) * ng + zg * hreg[v];
        }

        {
            const float hi0 = bfhi(hreg[0]), hi1 = bfhi(hreg[1]);
            const float hi2 = bfhi(hreg[2]), hi3 = bfhi(hreg[3]);
            sm.hhp[nxt][hkc][gid][hslot]     = bfpack(hi0, hi1);
            sm.hhp[nxt][hkc][gid + 8][hslot] = bfpack(hi2, hi3);
            sm.hlp[nxt][hkc][gid][hslot]     = bfpack(hreg[0] - hi0, hreg[1] - hi1);
            sm.hlp[nxt][hkc][gid + 8][hslot] = bfpack(hreg[2] - hi2, hreg[3] - hi3);
        }
        *reinterpret_cast<float2*>(
            &states[((long)(b0 + gid) * (TT + 1) + t + 1) * SS + c]) =
            make_float2(hreg[0], hreg[1]);
        *reinterpret_cast<float2*>(
            &states[((long)(b0 + gid + 8) * (TT + 1) + t + 1) * SS + c]) =
            make_float2(hreg[2], hreg[3]);
        if (dopref) {
            const float h0 = bfhi(pref.x), h1 = bfhi(pref.y);
            sm.ahp[nxt][akc][pr][aslot] = bfpack(h0, h1);
            sm.alp[nxt][akc][pr][aslot] = bfpack(pref.x - h0, pref.y - h1);
        }
        __syncthreads();
    }
}

// ---------------------------------------------------------------------------
// Kernel 2: heads. 512 threads, 2 CTAs/SM (64 regs), 128-row tile.
// L1 in two 128-col phases (32 accs live); W2 via 16B cp.async raw layout.
// Smem = 102912 B per CTA.
// ---------------------------------------------------------------------------
struct HeadSmem {
    float W1A1[16384];    // W1 packed [8][256][8] -> A1p packed [16][128][8]   65536 B
    float XpW2[8448];     // Xp packed [8][128][8] -> W2 quarter raw [64][132]  33792 B
    float b1s[256];
    float w2r[64];
    float w2s[64];
    float psum[2][2][128];
};

__global__ void __launch_bounds__(512, 2)
heads_kernel(const float* __restrict__ states,
             const float* __restrict__ dec_w1, const float* __restrict__ dec_b1,
             const float* __restrict__ dec_w2, const float* __restrict__ dec_b2,
             const float* __restrict__ rew_w1, const float* __restrict__ rew_b1,
             const float* __restrict__ rew_w2, const float* __restrict__ rew_b2,
             const float* __restrict__ saf_w1, const float* __restrict__ saf_b1,
             const float* __restrict__ saf_w2, const float* __restrict__ saf_b2,
             float* __restrict__ obs, float* __restrict__ rew,
             float* __restrict__ saf) {
    extern __shared__ char smem_raw[];
    HeadSmem& sm = *reinterpret_cast<HeadSmem*>(smem_raw);
    const int tid = threadIdx.x;
    const int m0 = blockIdx.x * 128;

    // ---- prologue staging ----
    for (int i = tid; i < 128 * 16; i += 512) {
        const int r = i >> 4, c4 = (i & 15) * 4;
        const int m = m0 + r, b = m >> 7, t = m & 127;
        const float4 v = *reinterpret_cast<const float4*>(
            &states[((long)b * (TT + 1) + t + 1) * SS + c4]);
        float* p = &sm.XpW2[(c4 >> 3) * 1024 + r * 8];
        if ((c4 & 4) == 0) {
            p[0] = tf32r(v.x); p[2] = tf32r(v.y); p[4] = tf32r(v.z); p[6] = tf32r(v.w);
        } else {
            p[1] = tf32r(v.x); p[3] = tf32r(v.y); p[5] = tf32r(v.z); p[7] = tf32r(v.w);
        }
    }
    for (int i = tid; i < 256 * 64; i += 512) {
        const int n = i >> 6, k = i & 63;
        float wv;
        if (n < 128)      wv = dec_w1[n * 64 + k];
        else if (n < 192) wv = rew_w1[(n - 128) * 64 + k];
        else              wv = saf_w1[(n - 192) * 64 + k];
        sm.W1A1[(k >> 3) * 2048 + n * 8 + pidx(k & 7)] = tf32r(wv);
    }
    for (int i = tid; i < 256; i += 512)
        sm.b1s[i] = (i < 128) ? dec_b1[i] : ((i < 192) ? rew_b1[i - 128] : saf_b1[i - 192]);
    for (int i = tid; i < 64; i += 512) { sm.w2r[i] = rew_w2[i]; sm.w2s[i] = saf_w2[i]; }
    __syncthreads();

    const int lane = tid & 31;
    const int w = tid >> 5;        // 16 warps
    const int wr = w & 3;          // 4 row groups of 32
    const int wcl = w >> 2;        // 4 col groups of 32 (per 128-col phase)
    const int gid = lane >> 2;
    const int t4 = lane & 3;
    const int i0p = pidx(t4 * 2);
    const int i1p = pidx(t4 * 2 + 1);

    float acc[2][4][4];

    // ---- L1 phase A: rew/saf cols (128..255) ----
    #pragma unroll
    for (int mt = 0; mt < 2; ++mt)
        #pragma unroll
        for (int nt = 0; nt < 4; ++nt)
            #pragma unroll
            for (int q = 0; q < 4; ++q) acc[mt][nt][q] = 0.f;

    #pragma unroll
    for (int ks = 0; ks < 8; ++ks) {
        uint32_t a[2][4];
        #pragma unroll
        for (int mt = 0; mt < 2; ++mt) {
            const int R = wr * 32 + mt * 16;
            const float2 f0 = *reinterpret_cast<const float2*>(
                &sm.XpW2[ks * 1024 + (R + gid) * 8 + 2 * t4]);
            const float2 f1 = *reinterpret_cast<const float2*>(
                &sm.XpW2[ks * 1024 + (R + gid + 8) * 8 + 2 * t4]);
            a[mt][0] = __float_as_uint(f0.x); a[mt][1] = __float_as_uint(f1.x);
            a[mt][2] = __float_as_uint(f0.y); a[mt][3] = __float_as_uint(f1.y);
        }
        #pragma unroll
        for (int nt = 0; nt < 4; ++nt) {
            const int n0 = 128 + wcl * 32 + nt * 8;
            const float2 bv = *reinterpret_cast<const float2*>(
                &sm.W1A1[ks * 2048 + (n0 + gid) * 8 + 2 * t4]);
            mma_tf32(acc[0][nt], a[0], __float_as_uint(bv.x), __float_as_uint(bv.y));
            mma_tf32(acc[1][nt], a[1], __float_as_uint(bv.x), __float_as_uint(bv.y));
        }
    }
    // psum epilogue (all 16 warps): wcl 0,1 -> rew; 2,3 -> saf
    {
        const int head = wcl >> 1;
        const int wl = wcl & 1;
        const float* w2v = head ? sm.w2s : sm.w2r;
        const int bbase = 128 + head * 64;
        #pragma unroll
        for (int mt = 0; mt < 2; ++mt) {
            float plo = 0.f, phi = 0.f;
            #pragma unroll
            for (int nt = 0; nt < 4; ++nt) {
                const int l = wl * 32 + nt * 8 + t4 * 2;
                const float bA = sm.b1s[bbase + l], bBv = sm.b1s[bbase + l + 1];
                const float v00 = fmaxf(acc[mt][nt][0] + bA, 0.f);
                const float v01 = fmaxf(acc[mt][nt][1] + bBv, 0.f);
                const float v10 = fmaxf(acc[mt][nt][2] + bA, 0.f);
                const float v11 = fmaxf(acc[mt][nt][3] + bBv, 0.f);
                plo = fmaf(v00, w2v[l], fmaf(v01, w2v[l + 1], plo));
                phi = fmaf(v10, w2v[l], fmaf(v11, w2v[l + 1], phi));
            }
            plo += __shfl_xor_sync(0xFFFFFFFFu, plo, 1);
            plo += __shfl_xor_sync(0xFFFFFFFFu, plo, 2);
            phi += __shfl_xor_sync(0xFFFFFFFFu, phi, 1);
            phi += __shfl_xor_sync(0xFFFFFFFFu, phi, 2);
            if (t4 == 0) {
                const int R = wr * 32 + mt * 16;
                sm.psum[head][wl][R + gid]     = plo;
                sm.psum[head][wl][R + gid + 8] = phi;
            }
        }
    }

    // ---- L1 phase B: dec cols (0..127) ----
    #pragma unroll
    for (int mt = 0; mt < 2; ++mt)
        #pragma unroll
        for (int nt = 0; nt < 4; ++nt)
            #pragma unroll
            for (int q = 0; q < 4; ++q) acc[mt][nt][q] = 0.f;

    #pragma unroll
    for (int ks = 0; ks < 8; ++ks) {
        uint32_t a[2][4];
        #pragma unroll
        for (int mt = 0; mt < 2; ++mt) {
            const int R = wr * 32 + mt * 16;
            const float2 f0 = *reinterpret_cast<const float2*>(
                &sm.XpW2[ks * 1024 + (R + gid) * 8 + 2 * t4]);
            const float2 f1 = *reinterpret_cast<const float2*>(
                &sm.XpW2[ks * 1024 + (R + gid + 8) * 8 + 2 * t4]);
            a[mt][0] = __float_as_uint(f0.x); a[mt][1] = __float_as_uint(f1.x);
            a[mt][2] = __float_as_uint(f0.y); a[mt][3] = __float_as_uint(f1.y);
        }
        #pragma unroll
        for (int nt = 0; nt < 4; ++nt) {
            const int n0 = wcl * 32 + nt * 8;
            const float2 bv = *reinterpret_cast<const float2*>(
                &sm.W1A1[ks * 2048 + (n0 + gid) * 8 + 2 * t4]);
            mma_tf32(acc[0][nt], a[0], __float_as_uint(bv.x), __float_as_uint(bv.y));
            mma_tf32(acc[1][nt], a[1], __float_as_uint(bv.x), __float_as_uint(bv.y));
        }
    }
    __syncthreads();   // all W1/Xp reads + psum writes complete

    // async-stage W2 quarter 0 into XpW2 (raw [64][132], 16B chunks)
    const uint32_t bq = (uint32_t)__cvta_generic_to_shared(&sm.XpW2[0]);
    for (int i = tid; i < 64 * 32; i += 512) {
        const int n = i >> 5, kc4 = (i & 31) * 4;
        cp_async16(bq + 4u * (n * 132 + kc4), &dec_w2[n * 128 + kc4]);
    }
    asm volatile("cp.async.commit_group;");

    // A1p epilogue (overwrite W1 region)
    #pragma unroll
    for (int mt = 0; mt < 2; ++mt) {
        const int R = wr * 32 + mt * 16;
        #pragma unroll
        for (int nt = 0; nt < 4; ++nt) {
            const int ks2 = wcl * 4 + nt;
            const int col = wcl * 32 + nt * 8 + t4 * 2;
            const float bA = sm.b1s[col], bBv = sm.b1s[col + 1];
            sm.W1A1[ks2 * 1024 + (R + gid) * 8 + i0p]     = tf32r(fmaxf(acc[mt][nt][0] + bA, 0.f));
            sm.W1A1[ks2 * 1024 + (R + gid) * 8 + i1p]     = tf32r(fmaxf(acc[mt][nt][1] + bBv, 0.f));
            sm.W1A1[ks2 * 1024 + (R + gid + 8) * 8 + i0p] = tf32r(fmaxf(acc[mt][nt][2] + bA, 0.f));
            sm.W1A1[ks2 * 1024 + (R + gid + 8) * 8 + i1p] = tf32r(fmaxf(acc[mt][nt][3] + bBv, 0.f));
        }
    }

    // finalize rew/saf
    if (tid < 256) {
        const int head = tid >> 7, r = tid & 127;
        const float b2 = head ? __ldg(&saf_b2[0]) : __ldg(&rew_b2[0]);
        (head ? saf : rew)[m0 + r] = sm.psum[head][0][r] + sm.psum[head][1][r] + b2;
    }

    asm volatile("cp.async.wait_group 0;" ::: "memory");
    __syncthreads();   // A1p visible + quarter 0 loaded

    // ---- Layer 2: 4 quarters of 64 cols, single-buffered raw W2 ----
    for (int q = 0; q < 4; ++q) {
        float acc2[2][2][4];
        #pragma unroll
        for (int mt = 0; mt < 2; ++mt)
            #pragma unroll
            for (int nt = 0; nt < 2; ++nt)
                #pragma unroll
                for (int qq = 0; qq < 4; ++qq) acc2[mt][nt][qq] = 0.f;

        #pragma unroll
        for (int ks = 0; ks < 16; ++ks) {
            uint32_t a[2][4];
            #pragma unroll
            for (int mt = 0; mt < 2; ++mt) {
                const int R = wr * 32 + mt * 16;
                const float2 f0 = *reinterpret_cast<const float2*>(
                    &sm.W1A1[ks * 1024 + (R + gid) * 8 + 2 * t4]);
                const float2 f1 = *reinterpret_cast<const float2*>(
                    &sm.W1A1[ks * 1024 + (R + gid + 8) * 8 + 2 * t4]);
                a[mt][0] = __float_as_uint(f0.x); a[mt][1] = __float_as_uint(f1.x);
                a[mt][2] = __float_as_uint(f0.y); a[mt][3] = __float_as_uint(f1.y);
            }
            #pragma unroll
            for (int nt = 0; nt < 2; ++nt) {
                const int nl = wcl * 16 + nt * 8;
                const uint32_t bb0 = __float_as_uint(sm.XpW2[(nl + gid) * 132 + ks * 8 + t4]);
                const uint32_t bb1 = __float_as_uint(sm.XpW2[(nl + gid) * 132 + ks * 8 + t4 + 4]);
                mma_tf32(acc2[0][nt], a[0], bb0, bb1);
                mma_tf32(acc2[1][nt], a[1], bb0, bb1);
            }
        }
        #pragma unroll
        for (int mt = 0; mt < 2; ++mt) {
            const int R = wr * 32 + mt * 16;
            #pragma unroll
            for (int nt = 0; nt < 2; ++nt) {
                const int cg = q * 64 + wcl * 16 + nt * 8 + t4 * 2;
                const float2 b2v = *reinterpret_cast<const float2*>(&dec_b2[cg]);
                *reinterpret_cast<float2*>(&obs[(long)(m0 + R + gid) * OO + cg]) =
                    make_float2(acc2[mt][nt][0] + b2v.x, acc2[mt][nt][1] + b2v.y);
                *reinterpret_cast<float2*>(&obs[(long)(m0 + R + gid + 8) * OO + cg]) =
                    make_float2(acc2[mt][nt][2] + b2v.x, acc2[mt][nt][3] + b2v.y);
            }
        }
        if (q < 3) {
            __syncthreads();   // buffer reads done
            for (int i = tid; i < 64 * 32; i += 512) {
                const int n = i >> 5, kc4 = (i & 31) * 4;
                cp_async16(bq + 4u * (n * 132 + kc4),
                           &dec_w2[((q + 1) * 64 + n) * 128 + kc4]);
            }
            asm volatile("cp.async.commit_group;");
            asm volatile("cp.async.wait_group 0;" ::: "memory");
            __syncthreads();   // next quarter visible
        }
    }
}

// ---------------------------------------------------------------------------
extern "C" void kernel_launch(void* const* d_in, const int* in_sizes, int n_in,
                              void* d_out, int out_size) {
    const float* initial_state = (const float*)d_in[0];
    const float* actions = (const float*)d_in[1];
    const float* W_ih = (const float*)d_in[2];
    const float* W_hh = (const float*)d_in[3];
    const float* b_ih = (const float*)d_in[4];
    const float* b_hh = (const float*)d_in[5];
    const float* dec_w1 = (const float*)d_in[6];
    const float* dec_b1 = (const float*)d_in[7];
    const float* dec_w2 = (const float*)d_in[8];
    const float* dec_b2 = (const float*)d_in[9];
    const float* rew_w1 = (const float*)d_in[10];
    const float* rew_b1 = (const float*)d_in[11];
    const float* rew_w2 = (const float*)d_in[12];
    const float* rew_b2 = (const float*)d_in[13];
    const float* saf_w1 = (const float*)d_in[14];
    const float* saf_b1 = (const float*)d_in[15];
    const float* saf_w2 = (const float*)d_in[16];
    const float* saf_b2 = (const float*)d_in[17];

    float* out = (float*)d_out;
    float* states = out;
    float* obs = out + (long)BB * (TT + 1) * SS;
    float* rew = obs + (long)BB * TT * OO;
    float* saf = rew + (long)BB * TT;

    cudaFuncSetAttribute(scan_kernel, cudaFuncAttributeMaxDynamicSharedMemorySize,
                         (int)sizeof(ScanSmem));
    cudaFuncSetAttribute(heads_kernel, cudaFuncAttributeMaxDynamicSharedMemorySize,
                         (int)sizeof(HeadSmem));

    scan_kernel<<<BB / 16, 256, sizeof(ScanSmem)>>>(
        initial_state, actions, W_ih, W_hh, b_ih, b_hh, states);
    heads_kernel<<<(BB * TT) / 128, 512, sizeof(HeadSmem)>>>(
        states, dec_w1, dec_b1, dec_w2, dec_b2,
        rew_w1, rew_b1, rew_w2, rew_b2,
        saf_w1, saf_b1, saf_w2, saf_b2,
        obs, rew, saf);
}

// round 17
// speedup vs baseline: 1.3453x; 1.0780x over previous
#include <cuda_runtime.h>
#include <cuda_bf16.h>
#include <cstdint>
#include <math.h>

#define BB 2048
#define TT 128
#define SS 64
#define AA 32
#define G3 192
#define HH 128
#define OO 256

#define DEV __device__ __forceinline__

DEV uint32_t tf32b(float x) {
    uint32_t u;
    asm("cvt.rna.tf32.f32 %0, %1;" : "=r"(u) : "f"(x));
    return u;
}
DEV float tf32r(float x) { return __uint_as_float(tf32b(x)); }

// packed pair index: element u (0..7) of an 8-group -> slot in float2-pair array
DEV int pidx(int u) { return (u < 4) ? (u << 1) : (((u - 4) << 1) | 1); }

DEV float bfhi(float x) { return __bfloat162float(__float2bfloat16_rn(x)); }
DEV uint32_t bfpack(float x, float y) {
    __nv_bfloat162 t = __floats2bfloat162_rn(x, y);
    return *reinterpret_cast<uint32_t*>(&t);
}

DEV void cp_async16(uint32_t smem_addr, const void* gptr) {
    asm volatile("cp.async.cg.shared.global [%0], [%1], 16;"
                 :: "r"(smem_addr), "l"(gptr));
}

DEV void mma_tf32(float* d, const uint32_t* a, uint32_t b0, uint32_t b1) {
    asm volatile(
        "mma.sync.aligned.m16n8k8.row.col.f32.tf32.tf32.f32 "
        "{%0,%1,%2,%3}, {%4,%5,%6,%7}, {%8,%9}, {%0,%1,%2,%3};"
        : "+f"(d[0]), "+f"(d[1]), "+f"(d[2]), "+f"(d[3])
        : "r"(a[0]), "r"(a[1]), "r"(a[2]), "r"(a[3]), "r"(b0), "r"(b1));
}

DEV void mma_bf16(float* d, const uint32_t* a, uint32_t b0, uint32_t b1) {
    asm volatile(
        "mma.sync.aligned.m16n8k16.row.col.f32.bf16.bf16.f32 "
        "{%0,%1,%2,%3}, {%4,%5,%6,%7}, {%8,%9}, {%0,%1,%2,%3};"
        : "+f"(d[0]), "+f"(d[1]), "+f"(d[2]), "+f"(d[3])
        : "r"(a[0]), "r"(a[1]), "r"(a[2]), "r"(a[3]), "r"(b0), "r"(b1));
}

// ---------------------------------------------------------------------------
// Kernel 1: GRU scan, bf16 mma.m16n8k16. 128 CTAs x 16 rows, 256 threads.
// n-gate: full x3 (hi*hi + lo*hi + hi*lo). r/z gates: x2 (weight-residual
// term dropped — sigmoid + z-contraction absorb the 2^-9 relative error).
// ---------------------------------------------------------------------------
struct ScanSmem {
    uint32_t hhp[2][4][16][8];
    uint32_t hlp[2][4][16][8];
    uint32_t ahp[2][2][16][8];
    uint32_t alp[2][2][16][8];
    uint32_t loIp[6][192][8];
    uint32_t loHp[4][192][8];
};

__global__ void __launch_bounds__(256, 1)
scan_kernel(const float* __restrict__ initial_state,
            const float* __restrict__ actions,
            const float* __restrict__ W_ih,
            const float* __restrict__ W_hh,
            const float* __restrict__ b_ih,
            const float* __restrict__ b_hh,
            float* __restrict__ states) {
    extern __shared__ char smem_raw[];
    ScanSmem& sm = *reinterpret_cast<ScanSmem*>(smem_raw);
    const int tid = threadIdx.x;
    const int w = tid >> 5;
    const int lane = tid & 31;
    const int gid = lane >> 2;
    const int t4 = lane & 3;
    const int b0 = blockIdx.x * 16;

    for (int i = tid; i < 192 * 48; i += 256) {
        const int n = i / 48, p = i % 48;
        const float v0 = W_ih[n * 96 + 2 * p];
        const float v1 = W_ih[n * 96 + 2 * p + 1];
        sm.loIp[p >> 3][n][pidx(p & 7)] = bfpack(v0 - bfhi(v0), v1 - bfhi(v1));
    }
    for (int i = tid; i < 192 * 32; i += 256) {
        const int n = i / 32, p = i % 32;
        const float v0 = W_hh[n * 64 + 2 * p];
        const float v1 = W_hh[n * 64 + 2 * p + 1];
        sm.loHp[p >> 3][n][pidx(p & 7)] = bfpack(v0 - bfhi(v0), v1 - bfhi(v1));
    }

    uint32_t BI[3][6][2], BH[3][4][2];
    #pragma unroll
    for (int ti = 0; ti < 3; ++ti) {
        const int n = w * 8 + ti * 64 + gid;
        #pragma unroll
        for (int kc = 0; kc < 6; ++kc) {
            const int k0 = kc * 16 + 2 * t4;
            BI[ti][kc][0] = bfpack(bfhi(W_ih[n * 96 + k0]),     bfhi(W_ih[n * 96 + k0 + 1]));
            BI[ti][kc][1] = bfpack(bfhi(W_ih[n * 96 + k0 + 8]), bfhi(W_ih[n * 96 + k0 + 9]));
        }
        #pragma unroll
        for (int kc = 0; kc < 4; ++kc) {
            const int k0 = kc * 16 + 2 * t4;
            BH[ti][kc][0] = bfpack(bfhi(W_hh[n * 64 + k0]),     bfhi(W_hh[n * 64 + k0 + 1]));
            BH[ti][kc][1] = bfpack(bfhi(W_hh[n * 64 + k0 + 8]), bfhi(W_hh[n * 64 + k0 + 9]));
        }
    }

    const int c = w * 8 + t4 * 2;
    const float br_[2]  = {b_ih[c] + b_hh[c],           b_ih[c + 1] + b_hh[c + 1]};
    const float bz_[2]  = {b_ih[64 + c] + b_hh[64 + c], b_ih[65 + c] + b_hh[65 + c]};
    const float biN_[2] = {b_ih[128 + c], b_ih[129 + c]};
    const float bhN_[2] = {b_hh[128 + c], b_hh[129 + c]};

    for (int i = tid; i < 16 * 32; i += 256) {
        const int r = i >> 5, p = i & 31;
        const float v0 = initial_state[(long)(b0 + r) * SS + 2 * p];
        const float v1 = initial_state[(long)(b0 + r) * SS + 2 * p + 1];
        states[(long)(b0 + r) * ((TT + 1) * SS) + 2 * p]     = v0;
        states[(long)(b0 + r) * ((TT + 1) * SS) + 2 * p + 1] = v1;
        const float h0 = bfhi(v0), h1 = bfhi(v1);
        sm.hhp[0][p >> 3][r][pidx(p & 7)] = bfpack(h0, h1);
        sm.hlp[0][p >> 3][r][pidx(p & 7)] = bfpack(v0 - h0, v1 - h1);
    }
    float hreg[4];
    hreg[0] = initial_state[(long)(b0 + gid) * SS + c];
    hreg[1] = initial_state[(long)(b0 + gid) * SS + c + 1];
    hreg[2] = initial_state[(long)(b0 + gid + 8) * SS + c];
    hreg[3] = initial_state[(long)(b0 + gid + 8) * SS + c + 1];

    const int pr = tid >> 4;
    const int pp = tid & 15;
    const int akc = pp >> 3, aslot = pidx(pp & 7);
    {
        const float2 v = *reinterpret_cast<const float2*>(
            &actions[((long)(b0 + pr) * TT) * AA + 2 * pp]);
        const float h0 = bfhi(v.x), h1 = bfhi(v.y);
        sm.ahp[0][akc][pr][aslot] = bfpack(h0, h1);
        sm.alp[0][akc][pr][aslot] = bfpack(v.x - h0, v.y - h1);
    }
    __syncthreads();

    const int hkc   = (w * 4 + t4) >> 3;
    const int hslot = pidx((w * 4 + t4) & 7);

    for (int t = 0; t < TT; ++t) {
        const int cur = t & 1, nxt = cur ^ 1;
        const bool dopref = (t + 1 < TT);
        float2 pref = make_float2(0.f, 0.f);
        if (dopref)
            pref = *reinterpret_cast<const float2*>(
                &actions[((long)(b0 + pr) * TT + (t + 1)) * AA + 2 * pp]);

        float aR[4]  = {0.f, 0.f, 0.f, 0.f};
        float aZ[4]  = {0.f, 0.f, 0.f, 0.f};
        float aNI[4] = {0.f, 0.f, 0.f, 0.f};
        float aNH[4] = {0.f, 0.f, 0.f, 0.f};

        #pragma unroll
        for (int kc = 0; kc < 6; ++kc) {
            uint2 h0, h1, l0, l1;
            if (kc < 4) {
                h0 = *reinterpret_cast<const uint2*>(&sm.hhp[cur][kc][gid][2 * t4]);
                h1 = *reinterpret_cast<const uint2*>(&sm.hhp[cur][kc][gid + 8][2 * t4]);
                l0 = *reinterpret_cast<const uint2*>(&sm.hlp[cur][kc][gid][2 * t4]);
                l1 = *reinterpret_cast<const uint2*>(&sm.hlp[cur][kc][gid + 8][2 * t4]);
            } else {
                h0 = *reinterpret_cast<const uint2*>(&sm.ahp[cur][kc - 4][gid][2 * t4]);
                h1 = *reinterpret_cast<const uint2*>(&sm.ahp[cur][kc - 4][gid + 8][2 * t4]);
                l0 = *reinterpret_cast<const uint2*>(&sm.alp[cur][kc - 4][gid][2 * t4]);
                l1 = *reinterpret_cast<const uint2*>(&sm.alp[cur][kc - 4][gid + 8][2 * t4]);
            }
            const uint32_t ah[4] = {h0.x, h1.x, h0.y, h1.y};
            const uint32_t al[4] = {l0.x, l1.x, l0.y, l1.y};

            #pragma unroll
            for (int ti = 0; ti < 3; ++ti) {
                float* acc = (ti == 0) ? aR : (ti == 1) ? aZ : aNI;
                mma_bf16(acc, ah, BI[ti][kc][0], BI[ti][kc][1]);
                mma_bf16(acc, al, BI[ti][kc][0], BI[ti][kc][1]);
                if (ti == 2) {   // weight-residual term: n-gate only
                    const int n = w * 8 + 128 + gid;
                    const uint2 bl = *reinterpret_cast<const uint2*>(&sm.loIp[kc][n][2 * t4]);
                    mma_bf16(acc, ah, bl.x, bl.y);
                }
            }
            if (kc < 4) {
                #pragma unroll
                for (int ti = 0; ti < 3; ++ti) {
                    float* acc = (ti == 0) ? aR : (ti == 1) ? aZ : aNH;
                    mma_bf16(acc, ah, BH[ti][kc][0], BH[ti][kc][1]);
                    mma_bf16(acc, al, BH[ti][kc][0], BH[ti][kc][1]);
                    if (ti == 2) {
                        const int n = w * 8 + 128 + gid;
                        const uint2 bl = *reinterpret_cast<const uint2*>(&sm.loHp[kc][n][2 * t4]);
                        mma_bf16(acc, ah, bl.x, bl.y);
                    }
                }
            }
        }

        #pragma unroll
        for (int v = 0; v < 4; ++v) {
            const int p = v & 1;
            const float sr = aR[v] + br_[p];
            const float sz = aZ[v] + bz_[p];
            const float rg = __fdividef(1.f, 1.f + __expf(-sr));
            const float zg = __fdividef(1.f, 1.f + __expf(-sz));
            const float narg = aNI[v] + biN_[p] + rg * (aNH[v] + bhN_[p]);
            const float e2 = __expf(2.f * narg);
            const float ng = 1.f - __fdividef(2.f, e2 + 1.f);
            hreg[v] = (1.f - zg) * ng + zg * hreg[v];
        }

        {
            const float hi0 = bfhi(hreg[0]), hi1 = bfhi(hreg[1]);
            const float hi2 = bfhi(hreg[2]), hi3 = bfhi(hreg[3]);
            sm.hhp[nxt][hkc][gid][hslot]     = bfpack(hi0, hi1);
            sm.hhp[nxt][hkc][gid + 8][hslot] = bfpack(hi2, hi3);
            sm.hlp[nxt][hkc][gid][hslot]     = bfpack(hreg[0] - hi0, hreg[1] - hi1);
            sm.hlp[nxt][hkc][gid + 8][hslot] = bfpack(hreg[2] - hi2, hreg[3] - hi3);
        }
        *reinterpret_cast<float2*>(
            &states[((long)(b0 + gid) * (TT + 1) + t + 1) * SS + c]) =
            make_float2(hreg[0], hreg[1]);
        *reinterpret_cast<float2*>(
            &states[((long)(b0 + gid + 8) * (TT + 1) + t + 1) * SS + c]) =
            make_float2(hreg[2], hreg[3]);
        if (dopref) {
            const float h0 = bfhi(pref.x), h1 = bfhi(pref.y);
            sm.ahp[nxt][akc][pr][aslot] = bfpack(h0, h1);
            sm.alp[nxt][akc][pr][aslot] = bfpack(pref.x - h0, pref.y - h1);
        }
        __syncthreads();
    }
}

// ---------------------------------------------------------------------------
// Kernel 2: heads. 512 threads, 2 CTAs/SM (64 regs), 128-row tile.
// Round-15 proven config (X/W1/A1 RN-rounded, W2 raw via cp.async16) +
// streaming obs stores. Smem = 102912 B per CTA.
// ---------------------------------------------------------------------------
struct HeadSmem {
    float W1A1[16384];    // W1 packed [8][256][8] -> A1p packed [16][128][8]
    float XpW2[8448];     // Xp packed [8][128][8] -> W2 quarter raw [64][132]
    float b1s[256];
    float w2r[64];
    float w2s[64];
    float psum[2][2][128];
};

__global__ void __launch_bounds__(512, 2)
heads_kernel(const float* __restrict__ states,
             const float* __restrict__ dec_w1, const float* __restrict__ dec_b1,
             const float* __restrict__ dec_w2, const float* __restrict__ dec_b2,
             const float* __restrict__ rew_w1, const float* __restrict__ rew_b1,
             const float* __restrict__ rew_w2, const float* __restrict__ rew_b2,
             const float* __restrict__ saf_w1, const float* __restrict__ saf_b1,
             const float* __restrict__ saf_w2, const float* __restrict__ saf_b2,
             float* __restrict__ obs, float* __restrict__ rew,
             float* __restrict__ saf) {
    extern __shared__ char smem_raw[];
    HeadSmem& sm = *reinterpret_cast<HeadSmem*>(smem_raw);
    const int tid = threadIdx.x;
    const int m0 = blockIdx.x * 128;

    // ---- prologue staging ----
    for (int i = tid; i < 128 * 16; i += 512) {
        const int r = i >> 4, c4 = (i & 15) * 4;
        const int m = m0 + r, b = m >> 7, t = m & 127;
        const float4 v = *reinterpret_cast<const float4*>(
            &states[((long)b * (TT + 1) + t + 1) * SS + c4]);
        float* p = &sm.XpW2[(c4 >> 3) * 1024 + r * 8];
        if ((c4 & 4) == 0) {
            p[0] = tf32r(v.x); p[2] = tf32r(v.y); p[4] = tf32r(v.z); p[6] = tf32r(v.w);
        } else {
            p[1] = tf32r(v.x); p[3] = tf32r(v.y); p[5] = tf32r(v.z); p[7] = tf32r(v.w);
        }
    }
    for (int i = tid; i < 256 * 64; i += 512) {
        const int n = i >> 6, k = i & 63;
        float wv;
        if (n < 128)      wv = dec_w1[n * 64 + k];
        else if (n < 192) wv = rew_w1[(n - 128) * 64 + k];
        else              wv = saf_w1[(n - 192) * 64 + k];
        sm.W1A1[(k >> 3) * 2048 + n * 8 + pidx(k & 7)] = tf32r(wv);
    }
    for (int i = tid; i < 256; i += 512)
        sm.b1s[i] = (i < 128) ? dec_b1[i] : ((i < 192) ? rew_b1[i - 128] : saf_b1[i - 192]);
    for (int i = tid; i < 64; i += 512) { sm.w2r[i] = rew_w2[i]; sm.w2s[i] = saf_w2[i]; }
    __syncthreads();

    const int lane = tid & 31;
    const int w = tid >> 5;        // 16 warps
    const int wr = w & 3;          // 4 row groups of 32
    const int wcl = w >> 2;        // 4 col groups of 32 (per 128-col phase)
    const int gid = lane >> 2;
    const int t4 = lane & 3;
    const int i0p = pidx(t4 * 2);
    const int i1p = pidx(t4 * 2 + 1);

    float acc[2][4][4];

    // ---- L1 phase A: rew/saf cols (128..255) ----
    #pragma unroll
    for (int mt = 0; mt < 2; ++mt)
        #pragma unroll
        for (int nt = 0; nt < 4; ++nt)
            #pragma unroll
            for (int q = 0; q < 4; ++q) acc[mt][nt][q] = 0.f;

    #pragma unroll
    for (int ks = 0; ks < 8; ++ks) {
        uint32_t a[2][4];
        #pragma unroll
        for (int mt = 0; mt < 2; ++mt) {
            const int R = wr * 32 + mt * 16;
            const float2 f0 = *reinterpret_cast<const float2*>(
                &sm.XpW2[ks * 1024 + (R + gid) * 8 + 2 * t4]);
            const float2 f1 = *reinterpret_cast<const float2*>(
                &sm.XpW2[ks * 1024 + (R + gid + 8) * 8 + 2 * t4]);
            a[mt][0] = __float_as_uint(f0.x); a[mt][1] = __float_as_uint(f1.x);
            a[mt][2] = __float_as_uint(f0.y); a[mt][3] = __float_as_uint(f1.y);
        }
        #pragma unroll
        for (int nt = 0; nt < 4; ++nt) {
            const int n0 = 128 + wcl * 32 + nt * 8;
            const float2 bv = *reinterpret_cast<const float2*>(
                &sm.W1A1[ks * 2048 + (n0 + gid) * 8 + 2 * t4]);
            mma_tf32(acc[0][nt], a[0], __float_as_uint(bv.x), __float_as_uint(bv.y));
            mma_tf32(acc[1][nt], a[1], __float_as_uint(bv.x), __float_as_uint(bv.y));
        }
    }
    // psum epilogue: wcl 0,1 -> rew; 2,3 -> saf
    {
        const int head = wcl >> 1;
        const int wl = wcl & 1;
        const float* w2v = head ? sm.w2s : sm.w2r;
        const int bbase = 128 + head * 64;
        #pragma unroll
        for (int mt = 0; mt < 2; ++mt) {
            float plo = 0.f, phi = 0.f;
            #pragma unroll
            for (int nt = 0; nt < 4; ++nt) {
                const int l = wl * 32 + nt * 8 + t4 * 2;
                const float bA = sm.b1s[bbase + l], bBv = sm.b1s[bbase + l + 1];
                const float v00 = fmaxf(acc[mt][nt][0] + bA, 0.f);
                const float v01 = fmaxf(acc[mt][nt][1] + bBv, 0.f);
                const float v10 = fmaxf(acc[mt][nt][2] + bA, 0.f);
                const float v11 = fmaxf(acc[mt][nt][3] + bBv, 0.f);
                plo = fmaf(v00, w2v[l], fmaf(v01, w2v[l + 1], plo));
                phi = fmaf(v10, w2v[l], fmaf(v11, w2v[l + 1], phi));
            }
            plo += __shfl_xor_sync(0xFFFFFFFFu, plo, 1);
            plo += __shfl_xor_sync(0xFFFFFFFFu, plo, 2);
            phi += __shfl_xor_sync(0xFFFFFFFFu, phi, 1);
            phi += __shfl_xor_sync(0xFFFFFFFFu, phi, 2);
            if (t4 == 0) {
                const int R = wr * 32 + mt * 16;
                sm.psum[head][wl][R + gid]     = plo;
                sm.psum[head][wl][R + gid + 8] = phi;
            }
        }
    }

    // ---- L1 phase B: dec cols (0..127) ----
    #pragma unroll
    for (int mt = 0; mt < 2; ++mt)
        #pragma unroll
        for (int nt = 0; nt < 4; ++nt)
            #pragma unroll
            for (int q = 0; q < 4; ++q) acc[mt][nt][q] = 0.f;

    #pragma unroll
    for (int ks = 0; ks < 8; ++ks) {
        uint32_t a[2][4];
        #pragma unroll
        for (int mt = 0; mt < 2; ++mt) {
            const int R = wr * 32 + mt * 16;
            const float2 f0 = *reinterpret_cast<const float2*>(
                &sm.XpW2[ks * 1024 + (R + gid) * 8 + 2 * t4]);
            const float2 f1 = *reinterpret_cast<const float2*>(
                &sm.XpW2[ks * 1024 + (R + gid + 8) * 8 + 2 * t4]);
            a[mt][0] = __float_as_uint(f0.x); a[mt][1] = __float_as_uint(f1.x);
            a[mt][2] = __float_as_uint(f0.y); a[mt][3] = __float_as_uint(f1.y);
        }
        #pragma unroll
        for (int nt = 0; nt < 4; ++nt) {
            const int n0 = wcl * 32 + nt * 8;
            const float2 bv = *reinterpret_cast<const float2*>(
                &sm.W1A1[ks * 2048 + (n0 + gid) * 8 + 2 * t4]);
            mma_tf32(acc[0][nt], a[0], __float_as_uint(bv.x), __float_as_uint(bv.y));
            mma_tf32(acc[1][nt], a[1], __float_as_uint(bv.x), __float_as_uint(bv.y));
        }
    }
    __syncthreads();   // all W1/Xp reads + psum writes complete

    // async-stage W2 quarter 0 into XpW2 (raw [64][132], 16B chunks)
    const uint32_t bq = (uint32_t)__cvta_generic_to_shared(&sm.XpW2[0]);
    for (int i = tid; i < 64 * 32; i += 512) {
        const int n = i >> 5, kc4 = (i & 31) * 4;
        cp_async16(bq + 4u * (n * 132 + kc4), &dec_w2[n * 128 + kc4]);
    }
    asm volatile("cp.async.commit_group;");

    // A1p epilogue (overwrite W1 region)
    #pragma unroll
    for (int mt = 0; mt < 2; ++mt) {
        const int R = wr * 32 + mt * 16;
        #pragma unroll
        for (int nt = 0; nt < 4; ++nt) {
            const int ks2 = wcl * 4 + nt;
            const int col = wcl * 32 + nt * 8 + t4 * 2;
            const float bA = sm.b1s[col], bBv = sm.b1s[col + 1];
            sm.W1A1[ks2 * 1024 + (R + gid) * 8 + i0p]     = tf32r(fmaxf(acc[mt][nt][0] + bA, 0.f));
            sm.W1A1[ks2 * 1024 + (R + gid) * 8 + i1p]     = tf32r(fmaxf(acc[mt][nt][1] + bBv, 0.f));
            sm.W1A1[ks2 * 1024 + (R + gid + 8) * 8 + i0p] = tf32r(fmaxf(acc[mt][nt][2] + bA, 0.f));
            sm.W1A1[ks2 * 1024 + (R + gid + 8) * 8 + i1p] = tf32r(fmaxf(acc[mt][nt][3] + bBv, 0.f));
        }
    }

    // finalize rew/saf
    if (tid < 256) {
        const int head = tid >> 7, r = tid & 127;
        const float b2 = head ? __ldg(&saf_b2[0]) : __ldg(&rew_b2[0]);
        (head ? saf : rew)[m0 + r] = sm.psum[head][0][r] + sm.psum[head][1][r] + b2;
    }

    asm volatile("cp.async.wait_group 0;" ::: "memory");
    __syncthreads();   // A1p visible + quarter 0 loaded

    // ---- Layer 2: 4 quarters of 64 cols, raw W2, streaming obs stores ----
    for (int q = 0; q < 4; ++q) {
        float acc2[2][2][4];
        #pragma unroll
        for (int mt = 0; mt < 2; ++mt)
            #pragma unroll
            for (int nt = 0; nt < 2; ++nt)
                #pragma unroll
                for (int qq = 0; qq < 4; ++qq) acc2[mt][nt][qq] = 0.f;

        #pragma unroll
        for (int ks = 0; ks < 16; ++ks) {
            uint32_t a[2][4];
            #pragma unroll
            for (int mt = 0; mt < 2; ++mt) {
                const int R = wr * 32 + mt * 16;
                const float2 f0 = *reinterpret_cast<const float2*>(
                    &sm.W1A1[ks * 1024 + (R + gid) * 8 + 2 * t4]);
                const float2 f1 = *reinterpret_cast<const float2*>(
                    &sm.W1A1[ks * 1024 + (R + gid + 8) * 8 + 2 * t4]);
                a[mt][0] = __float_as_uint(f0.x); a[mt][1] = __float_as_uint(f1.x);
                a[mt][2] = __float_as_uint(f0.y); a[mt][3] = __float_as_uint(f1.y);
            }
            #pragma unroll
            for (int nt = 0; nt < 2; ++nt) {
                const int nl = wcl * 16 + nt * 8;
                const uint32_t bb0 = __float_as_uint(sm.XpW2[(nl + gid) * 132 + ks * 8 + t4]);
                const uint32_t bb1 = __float_as_uint(sm.XpW2[(nl + gid) * 132 + ks * 8 + t4 + 4]);
                mma_tf32(acc2[0][nt], a[0], bb0, bb1);
                mma_tf32(acc2[1][nt], a[1], bb0, bb1);
            }
        }
        #pragma unroll
        for (int mt = 0; mt < 2; ++mt) {
            const int R = wr * 32 + mt * 16;
            #pragma unroll
            for (int nt = 0; nt < 2; ++nt) {
                const int cg = q * 64 + wcl * 16 + nt * 8 + t4 * 2;
                const float2 b2v = *reinterpret_cast<const float2*>(&dec_b2[cg]);
                __stcs(reinterpret_cast<float2*>(&obs[(long)(m0 + R + gid) * OO + cg]),
                       make_float2(acc2[mt][nt][0] + b2v.x, acc2[mt][nt][1] + b2v.y));
                __stcs(reinterpret_cast<float2*>(&obs[(long)(m0 + R + gid + 8) * OO + cg]),
                       make_float2(acc2[mt][nt][2] + b2v.x, acc2[mt][nt][3] + b2v.y));
            }
        }
        if (q < 3) {
            __syncthreads();   // buffer reads done
            for (int i = tid; i < 64 * 32; i += 512) {
                const int n = i >> 5, kc4 = (i & 31) * 4;
                cp_async16(bq + 4u * (n * 132 + kc4),
                           &dec_w2[((q + 1) * 64 + n) * 128 + kc4]);
            }
            asm volatile("cp.async.commit_group;");
            asm volatile("cp.async.wait_group 0;" ::: "memory");
            __syncthreads();   // next quarter visible
        }
    }
}

// ---------------------------------------------------------------------------
extern "C" void kernel_launch(void* const* d_in, const int* in_sizes, int n_in,
                              void* d_out, int out_size) {
    const float* initial_state = (const float*)d_in[0];
    const float* actions = (const float*)d_in[1];
    const float* W_ih = (const float*)d_in[2];
    const float* W_hh = (const float*)d_in[3];
    const float* b_ih = (const float*)d_in[4];
    const float* b_hh = (const float*)d_in[5];
    const float* dec_w1 = (const float*)d_in[6];
    const float* dec_b1 = (const float*)d_in[7];
    const float* dec_w2 = (const float*)d_in[8];
    const float* dec_b2 = (const float*)d_in[9];
    const float* rew_w1 = (const float*)d_in[10];
    const float* rew_b1 = (const float*)d_in[11];
    const float* rew_w2 = (const float*)d_in[12];
    const float* rew_b2 = (const float*)d_in[13];
    const float* saf_w1 = (const float*)d_in[14];
    const float* saf_b1 = (const float*)d_in[15];
    const float* saf_w2 = (const float*)d_in[16];
    const float* saf_b2 = (const float*)d_in[17];

    float* out = (float*)d_out;
    float* states = out;
    float* obs = out + (long)BB * (TT + 1) * SS;
    float* rew = obs + (long)BB * TT * OO;
    float* saf = rew + (long)BB * TT;

    cudaFuncSetAttribute(scan_kernel, cudaFuncAttributeMaxDynamicSharedMemorySize,
                         (int)sizeof(ScanSmem));
    cudaFuncSetAttribute(heads_kernel, cudaFuncAttributeMaxDynamicSharedMemorySize,
                         (int)sizeof(HeadSmem));

    scan_kernel<<<BB / 16, 256, sizeof(ScanSmem)>>>(
        initial_state, actions, W_ih, W_hh, b_ih, b_hh, states);
    heads_kernel<<<(BB * TT) / 128, 512, sizeof(HeadSmem)>>>(
        states, dec_w1, dec_b1, dec_w2, dec_b2,
        rew_w1, rew_b1, rew_w2, rew_b2,
        saf_w1, saf_b1, saf_w2, saf_b2,
        obs, rew, saf);
}